// round 15
// baseline (speedup 1.0000x reference)
#include <cuda_runtime.h>
#include <cuda_fp16.h>
#include <cstdint>
#include <math.h>

#define Bsz   1024
#define Az    5
#define Nz    16384
#define Dz    512
#define TOPK  50
#define NSTEP 5
#define MT    13          // max padded 128-row tiles
#define CAND_CAP 1024
#define MARGIN 0.006f
#define SIMS_DYN_SMEM (4 * 16384 + 1024)

// ---- scratch (device globals, no allocations) ----
__device__ float  g_kn[(size_t)Az * Nz * Dz];     // fp32 normalized keys (exact path)
__device__ __half g_kh[(size_t)Az * Nz * Dz];     // fp16 normalized keys (MMA path)
__device__ float  g_qn[Bsz * Dz];
__device__ __half g_qh[Bsz * Dz];
__device__ float  g_cur[Bsz * Dz];
__device__ __half g_simh[(size_t)Bsz * Nz];       // 32 MB approx sims
__device__ unsigned g_bmaxkey[Bsz * 128];         // per (row, 128-col block) max (sortable u16 key)
__device__ float  g_kdenom[Az * Nz];
__device__ float  g_qdenom[Bsz];
__device__ int    g_row_map[NSTEP][MT * 128];
__device__ int    g_tile_action[NSTEP][MT];

__device__ __forceinline__ uint32_t smem_u32(const void* p) {
    uint32_t a;
    asm("{ .reg .u64 t; cvta.to.shared.u64 t, %1; cvt.u32.u64 %0, t; }" : "=r"(a) : "l"(p));
    return a;
}

#define SMEM_SWZ(off) ((off) ^ (((off) >> 3) & 0x70))

__device__ __forceinline__ void cp_async16(uint32_t dst, const void* src, bool valid) {
    int sz = valid ? 16 : 0;
    asm volatile("cp.async.cg.shared.global [%0], [%1], 16, %2;"
                 :: "r"(dst), "l"(src), "r"(sz) : "memory");
}
#define CP_COMMIT() asm volatile("cp.async.commit_group;" ::: "memory")
#define CP_WAIT(n)  asm volatile("cp.async.wait_group %0;" :: "n"(n) : "memory")

__device__ __forceinline__ void ldmatrix_x4(uint32_t* r, uint32_t addr) {
    asm volatile("ldmatrix.sync.aligned.m8n8.x4.shared.b16 {%0,%1,%2,%3}, [%4];"
                 : "=r"(r[0]), "=r"(r[1]), "=r"(r[2]), "=r"(r[3]) : "r"(addr));
}
__device__ __forceinline__ void mma_16816(float* c, const uint32_t* a, uint32_t b0, uint32_t b1) {
    asm volatile(
        "mma.sync.aligned.m16n8k16.row.col.f32.f16.f16.f32 "
        "{%0,%1,%2,%3}, {%4,%5,%6,%7}, {%8,%9}, {%0,%1,%2,%3};"
        : "+f"(c[0]), "+f"(c[1]), "+f"(c[2]), "+f"(c[3])
        : "r"(a[0]), "r"(a[1]), "r"(a[2]), "r"(a[3]), "r"(b0), "r"(b1));
}

__device__ __forceinline__ float warp_sum(float v) {
#pragma unroll
    for (int o = 16; o; o >>= 1) v += __shfl_xor_sync(0xffffffffu, v, o);
    return v;
}

// Cephes/Eigen-style expf — numerics frozen from passing round
__device__ __forceinline__ float ref_exp(float x) {
    float m = floorf(fmaf(x, 1.44269504088896341f, 0.5f));
    float r = fmaf(m, -0.693359375f, x);
    r = fmaf(m, 2.12194440e-4f, r);
    float r2 = r * r;
    float p = 1.9875691500E-4f;
    p = fmaf(p, r, 1.3981999507E-3f);
    p = fmaf(p, r, 8.3334519073E-3f);
    p = fmaf(p, r, 4.1665795894E-2f);
    p = fmaf(p, r, 1.6666665459E-1f);
    p = fmaf(p, r, 5.0000001201E-1f);
    float y = fmaf(p, r2, r) + 1.0f;
    return ldexpf(y, (int)m);
}

__device__ __forceinline__ unsigned hsort16(unsigned h) {
    return (h & 0x8000u) ? (0xFFFFu & ~h) : (h | 0x8000u);
}
__device__ __forceinline__ float hkey2float(unsigned k) {
    unsigned hb = (k & 0x8000u) ? (k ^ 0x8000u) : (0xFFFFu & ~k);
    return __half2float(__ushort_as_half((unsigned short)hb));
}

// ---------------- row denominators ----------------
__global__ void row_denom_kernel(const float* __restrict__ X, int which, int nrows) {
    int r = blockIdx.x * blockDim.x + threadIdx.x;
    if (r >= nrows) return;
    const float4* p = (const float4*)(X + (size_t)r * Dz);
    float a[8];
#pragma unroll
    for (int j = 0; j < 8; j++) a[j] = 0.f;
    for (int i = 0; i < Dz / 8; i++) {
        float4 v0 = p[2 * i];
        float4 v1 = p[2 * i + 1];
        a[0] = fmaf(v0.x, v0.x, a[0]); a[1] = fmaf(v0.y, v0.y, a[1]);
        a[2] = fmaf(v0.z, v0.z, a[2]); a[3] = fmaf(v0.w, v0.w, a[3]);
        a[4] = fmaf(v1.x, v1.x, a[4]); a[5] = fmaf(v1.y, v1.y, a[5]);
        a[6] = fmaf(v1.z, v1.z, a[6]); a[7] = fmaf(v1.w, v1.w, a[7]);
    }
    float e0 = a[0] + a[4], e1 = a[1] + a[5], e2 = a[2] + a[6], e3 = a[3] + a[7];
    float f0 = e0 + e2, f1 = e1 + e3;
    float d = __fsqrt_rn(f0 + f1) + 1e-8f;
    if (which) g_qdenom[r] = d; else g_kdenom[r] = d;
}

// ---------------- normalize (IEEE div) + fp16 pack ----------------
__global__ void normalize_kernel(const float* __restrict__ X, int which, int n4) {
    float* Y = which ? g_qn : g_kn;
    __half* Yh = which ? g_qh : g_kh;
    const float* D = which ? g_qdenom : g_kdenom;
    for (int i = blockIdx.x * blockDim.x + threadIdx.x; i < n4; i += gridDim.x * blockDim.x) {
        float4 v = ((const float4*)X)[i];
        float d = D[i >> 7];
        float4 o;
        o.x = __fdiv_rn(v.x, d); o.y = __fdiv_rn(v.y, d);
        o.z = __fdiv_rn(v.z, d); o.w = __fdiv_rn(v.w, d);
        ((float4*)Y)[i] = o;
        __half2 h0 = __float22half2_rn(make_float2(o.x, o.y));
        __half2 h1 = __float22half2_rn(make_float2(o.z, o.w));
        uint2 pk;
        pk.x = *reinterpret_cast<unsigned*>(&h0);
        pk.y = *reinterpret_cast<unsigned*>(&h1);
        ((uint2*)Yh)[i] = pk;
    }
}

// ---------------- group batches by selected action ----------------
__global__ void group_kernel(const int* __restrict__ actions) {
    __shared__ int cnt[Az], cur[Az];
    int tid = threadIdx.x;
    for (int t = 0; t < NSTEP; t++) {
        if (tid < Az) cnt[tid] = 0;
        __syncthreads();
        for (int b = tid; b < Bsz; b += blockDim.x)
            atomicAdd(&cnt[actions[b * NSTEP + t]], 1);
        __syncthreads();
        if (tid == 0) {
            int off = 0;
            for (int a = 0; a < Az; a++) {
                cur[a] = off;
                off += ((cnt[a] + 127) >> 7) << 7;
            }
        }
        __syncthreads();
        for (int i = tid; i < MT * 128; i += blockDim.x) g_row_map[t][i] = -1;
        __syncthreads();
        for (int b = tid; b < Bsz; b += blockDim.x) {
            int a = actions[b * NSTEP + t];
            int p = atomicAdd(&cur[a], 1);
            g_row_map[t][p] = b;
        }
        if (tid < MT) {
            int mt = tid, act = -1, off = 0;
            for (int a = 0; a < Az; a++) {
                int len = ((cnt[a] + 127) >> 7) << 7;
                if (mt * 128 >= off && mt * 128 < off + len) act = a;
                off += len;
            }
            g_tile_action[t][mt] = act;
        }
        __syncthreads();
    }
}

// ---------------- HMMA fp16 approx GEMM + per-block row maxes ----------------
__global__ __launch_bounds__(256, 2) void sims_mma(int t) {
    extern __shared__ unsigned char dyn_smem[];
    __shared__ int rs[128];
    __shared__ unsigned s_rmax[2][128];

    int mt = blockIdx.y;
    int act = g_tile_action[t][mt];
    if (act < 0) return;
    int n0 = blockIdx.x * 128;

    int tid = threadIdx.x, wid = tid >> 5, lane = tid & 31;
    if (tid < 128) rs[tid] = g_row_map[t][mt * 128 + tid];
    __syncthreads();

    unsigned char* base = (unsigned char*)(((uintptr_t)dyn_smem + 1023) & ~(uintptr_t)1023);
    uint32_t sAu[2] = { smem_u32(base),         smem_u32(base + 16384) };
    uint32_t sBu[2] = { smem_u32(base + 32768), smem_u32(base + 49152) };

    int warp_m = wid >> 1, warp_n = wid & 1;
    int m_base = warp_m * 32, nb_base = warp_n * 64;

    const uint4* qb = (const uint4*)g_qh;
    const uint4* kb = (const uint4*)(g_kh + ((size_t)act * Nz + n0) * Dz);

    float c[2][8][4];
#pragma unroll
    for (int i = 0; i < 2; i++)
#pragma unroll
        for (int j = 0; j < 8; j++)
#pragma unroll
            for (int k = 0; k < 4; k++) c[i][j][k] = 0.f;

    int lrow = lane & 15, lslot = lane >> 4;

    int srow_[4], si4_[4], sar_[4];
    unsigned sw_[4];
#pragma unroll
    for (int rep = 0; rep < 4; rep++) {
        int idx = tid + rep * 256;
        srow_[rep] = idx >> 3;
        si4_[rep] = idx & 7;
        sar_[rep] = rs[srow_[rep]];
        sw_[rep] = SMEM_SWZ(srow_[rep] * 128 + si4_[rep] * 16);
    }

    auto stage = [&](int kc, int buf) {
#pragma unroll
        for (int rep = 0; rep < 4; rep++) {
            int ar = sar_[rep];
            cp_async16(sAu[buf] + sw_[rep],
                       qb + (size_t)(ar < 0 ? 0 : ar) * 64 + kc * 8 + si4_[rep], ar >= 0);
            cp_async16(sBu[buf] + sw_[rep],
                       kb + (size_t)srow_[rep] * 64 + kc * 8 + si4_[rep], true);
        }
        CP_COMMIT();
    };

    stage(0, 0);
#pragma unroll 1
    for (int kc = 0; kc < 8; kc++) {
        int buf = kc & 1;
        if (kc + 1 < 8) { stage(kc + 1, buf ^ 1); CP_WAIT(1); }
        else            { CP_WAIT(0); }
        __syncthreads();
#pragma unroll
        for (int k16 = 0; k16 < 4; k16++) {
            int slot16 = (2 * k16 + lslot) * 16;
            uint32_t a[2][4];
#pragma unroll
            for (int mi = 0; mi < 2; mi++) {
                int row = m_base + mi * 16 + lrow;
                ldmatrix_x4(a[mi], sAu[buf] + row * 128 + (slot16 ^ ((row & 7) << 4)));
            }
            uint32_t bf[4][4];
#pragma unroll
            for (int nb = 0; nb < 4; nb++) {
                int row = nb_base + nb * 16 + lrow;
                ldmatrix_x4(bf[nb], sBu[buf] + row * 128 + (slot16 ^ ((row & 7) << 4)));
            }
#pragma unroll
            for (int mi = 0; mi < 2; mi++)
#pragma unroll
                for (int nj = 0; nj < 8; nj++) {
                    int nb = nj >> 1, hi = nj & 1;
                    mma_16816(c[mi][nj], a[mi], bf[nb][hi], bf[nb][hi + 2]);
                }
        }
        __syncthreads();
    }

    // epilogue: store half sims + per-row block-max keys
    unsigned km[2][2];
    km[0][0] = km[0][1] = km[1][0] = km[1][1] = 0u;
#pragma unroll
    for (int mi = 0; mi < 2; mi++) {
        int r0 = rs[m_base + mi * 16 + (lane >> 2)];
        int r1 = rs[m_base + mi * 16 + (lane >> 2) + 8];
#pragma unroll
        for (int nj = 0; nj < 8; nj++) {
            int col = n0 + nb_base + nj * 8 + (lane & 3) * 2;
            __half2 h0 = __floats2half2_rn(c[mi][nj][0], c[mi][nj][1]);
            __half2 h1 = __floats2half2_rn(c[mi][nj][2], c[mi][nj][3]);
            unsigned u0 = *reinterpret_cast<unsigned*>(&h0);
            unsigned u1 = *reinterpret_cast<unsigned*>(&h1);
            km[mi][0] = max(km[mi][0], max(hsort16(u0 & 0xFFFFu), hsort16(u0 >> 16)));
            km[mi][1] = max(km[mi][1], max(hsort16(u1 & 0xFFFFu), hsort16(u1 >> 16)));
            if (r0 >= 0) *(unsigned*)(g_simh + (size_t)r0 * Nz + col) = u0;
            if (r1 >= 0) *(unsigned*)(g_simh + (size_t)r1 * Nz + col) = u1;
        }
    }
#pragma unroll
    for (int mi = 0; mi < 2; mi++)
#pragma unroll
        for (int rr = 0; rr < 2; rr++) {
            unsigned v = km[mi][rr];
            v = max(v, __shfl_xor_sync(0xffffffffu, v, 1));
            v = max(v, __shfl_xor_sync(0xffffffffu, v, 2));
            if ((lane & 3) == 0)
                s_rmax[warp_n][m_base + mi * 16 + (lane >> 2) + rr * 8] = v;
        }
    __syncthreads();
    if (tid < 128) {
        int r = rs[tid];
        if (r >= 0)
            g_bmaxkey[r * 128 + blockIdx.x] = max(s_rmax[0][tid], s_rmax[1][tid]);
    }
}

// ---------------- topk: block-max threshold -> 1 scan -> a50 refine -> exact rescoring ----------------
__global__ __launch_bounds__(256) void topk_kernel(const float* __restrict__ memv,
                                                   const int* __restrict__ actions, int t) {
    __shared__ unsigned s_bk[128];
    __shared__ unsigned char s_skip[128];
    __shared__ unsigned sh_T0, sh_a50;
    __shared__ float4 s_q4[Dz / 4];
    __shared__ int   s_cidx[CAND_CAP];
    __shared__ float s_cvala[CAND_CAP];   // approx values
    __shared__ float s_cval[CAND_CAP];    // exact values (or -inf)
    __shared__ int   s_cnt;
    __shared__ float s_val[TOPK];
    __shared__ int   s_idx[TOPK];
    __shared__ float s_cur[Dz];
    __shared__ float s_acc8[8];
    __shared__ float sh_denom;

    int b = blockIdx.x;
    int tid = threadIdx.x;
    const uint4* srow8 = (const uint4*)(g_simh + (size_t)b * Nz);

    if (tid == 0) { s_cnt = 0; sh_T0 = 0xFFFFFFFFu; sh_a50 = 0xFFFFFFFFu; }
    if (tid < 128) s_bk[tid] = g_bmaxkey[b * 128 + tid];
    for (int i = tid; i < Dz; i += 256)
        ((float*)s_q4)[i] = g_qn[(size_t)b * Dz + i];
    __syncthreads();

    // 50th-largest block max (M50 <= row's rank-50 value)
    if (tid < 128) {
        unsigned v = s_bk[tid];
        int cg = 0;
        for (int j = 0; j < 128; j++) cg += (s_bk[j] > v);
        if (cg <= 49) atomicMin(&sh_T0, v);
    }
    __syncthreads();
    float Tf = hkey2float(sh_T0) - MARGIN;
    if (tid < 128) s_skip[tid] = (hkey2float(s_bk[tid]) < Tf) ? 1 : 0;
    __syncthreads();

    // single candidate scan with block skipping
    for (int i8 = tid; i8 < Nz / 8; i8 += 256) {
        if (s_skip[i8 >> 4]) continue;
        uint4 v = srow8[i8];
        unsigned w[4] = {v.x, v.y, v.z, v.w};
#pragma unroll
        for (int c2 = 0; c2 < 4; c2++) {
            float2 f = __half22float2(*reinterpret_cast<__half2*>(&w[c2]));
            if (f.x >= Tf) {
                int p = atomicAdd(&s_cnt, 1);
                if (p < CAND_CAP) { s_cidx[p] = i8 * 8 + c2 * 2; s_cvala[p] = f.x; }
            }
            if (f.y >= Tf) {
                int p = atomicAdd(&s_cnt, 1);
                if (p < CAND_CAP) { s_cidx[p] = i8 * 8 + c2 * 2 + 1; s_cvala[p] = f.y; }
            }
        }
    }
    __syncthreads();
    int C = min(s_cnt, CAND_CAP);

    // a50 = 50th-largest approx value among candidates (== global approx rank-50)
    for (int c = tid; c < C; c += 256) {
        float v = s_cvala[c];
        int cg = 0;
        for (int j = 0; j < C; j++) cg += (s_cvala[j] > v);
        if (cg <= 49) {
            unsigned u = __float_as_uint(v);
            u = (u & 0x80000000u) ? ~u : (u | 0x80000000u);
            atomicMin(&sh_a50, u);
        }
    }
    __syncthreads();
    unsigned ua = sh_a50;
    ua = (ua & 0x80000000u) ? (ua ^ 0x80000000u) : ~ua;
    float ft = __uint_as_float(ua) - MARGIN;

    // exact fp32 rescoring of the refined set (d-ascending fmaf chain, frozen numerics)
    int a = actions[b * NSTEP + t];
    const float* knb = g_kn + (size_t)a * Nz * Dz;
    for (int c = tid; c < C; c += 256) {
        if (s_cvala[c] < ft) { s_cval[c] = -3.4e38f; continue; }
        const float4* kr = (const float4*)(knb + (size_t)s_cidx[c] * Dz);
        float acc = 0.f;
#pragma unroll 4
        for (int d4 = 0; d4 < Dz / 4; d4++) {
            float4 kv = __ldg(&kr[d4]);
            float4 qv = s_q4[d4];
            acc = fmaf(qv.x, kv.x, acc);
            acc = fmaf(qv.y, kv.y, acc);
            acc = fmaf(qv.z, kv.z, acc);
            acc = fmaf(qv.w, kv.w, acc);
        }
        s_cval[c] = acc;
    }
    __syncthreads();

    // exact ranking (value desc, index asc) into slots 0..49
    for (int c = tid; c < C; c += 256) {
        float v = s_cval[c];
        int id = s_cidx[c];
        int rank = 0;
        for (int j = 0; j < C; j++) {
            float vj = s_cval[j];
            rank += (vj > v) || (vj == v && s_cidx[j] < id);
        }
        if (rank < TOPK) { s_val[rank] = v; s_idx[rank] = id; }
    }
    __syncthreads();

    if (tid == 0) {
        float mx = s_val[0];
        float sum = 0.f;
        for (int k2 = 0; k2 < TOPK; k2++) {
            float e = ref_exp(s_val[k2] - mx);
            s_val[k2] = e;
            sum += e;
        }
        for (int k2 = 0; k2 < TOPK; k2++) s_val[k2] = __fdiv_rn(s_val[k2], sum);
    }
    __syncthreads();

    const float* vb = memv + (size_t)a * Nz * Dz;
    float a0 = 0.f, a1 = 0.f;
    int d0 = tid, d1 = tid + 256;
    for (int k2 = 0; k2 < TOPK; k2++) {
        const float* vr = vb + (size_t)s_idx[k2] * Dz;
        float w2 = s_val[k2];
        a0 = fmaf(w2, vr[d0], a0);
        a1 = fmaf(w2, vr[d1], a1);
    }
    s_cur[d0] = a0;
    s_cur[d1] = a1;
    g_cur[b * Dz + d0] = a0;
    g_cur[b * Dz + d1] = a1;
    __syncthreads();

    if (tid < 8) {
        float acc = 0.f;
        for (int i = 0; i < Dz / 8; i++) {
            float x = s_cur[8 * i + tid];
            acc = fmaf(x, x, acc);
        }
        s_acc8[tid] = acc;
    }
    __syncthreads();
    if (tid == 0) {
        float e0 = s_acc8[0] + s_acc8[4], e1 = s_acc8[1] + s_acc8[5];
        float e2 = s_acc8[2] + s_acc8[6], e3 = s_acc8[3] + s_acc8[7];
        float f0 = e0 + e2, f1 = e1 + e3;
        sh_denom = __fsqrt_rn(f0 + f1) + 1e-8f;
    }
    __syncthreads();
    float dn = sh_denom;
    float q0 = __fdiv_rn(a0, dn);
    float q1 = __fdiv_rn(a1, dn);
    g_qn[b * Dz + d0] = q0;
    g_qn[b * Dz + d1] = q1;
    g_qh[b * Dz + d0] = __float2half_rn(q0);
    g_qh[b * Dz + d1] = __float2half_rn(q1);
}

// ---------------- fused 3-layer MLP (512->256->128->1, elu) ----------------
__global__ __launch_bounds__(256) void mlp_kernel(const float* __restrict__ emb, int use_emb,
                                                  const float* __restrict__ W1, const float* __restrict__ b1,
                                                  const float* __restrict__ W2, const float* __restrict__ b2,
                                                  const float* __restrict__ W3, const float* __restrict__ b3,
                                                  float* __restrict__ out, int off, int stride) {
    __shared__ float Xs[8 * 512];
    __shared__ float H1[8 * 256];
    __shared__ float H2[8 * 128];
    const float* X = use_emb ? emb : g_cur;
    int tid = threadIdx.x;
    int b0 = blockIdx.x * 8;

    for (int i = tid; i < 8 * 512; i += 256) Xs[i] = X[(size_t)b0 * 512 + i];
    __syncthreads();
    {
        int j = tid;
        float acc[8];
#pragma unroll
        for (int bb = 0; bb < 8; bb++) acc[bb] = 0.f;
        for (int d = 0; d < 512; d += 4) {
            float w0 = W1[(d + 0) * 256 + j];
            float w1 = W1[(d + 1) * 256 + j];
            float w2v = W1[(d + 2) * 256 + j];
            float w3v = W1[(d + 3) * 256 + j];
#pragma unroll
            for (int bb = 0; bb < 8; bb++) {
                float4 x = *(const float4*)(&Xs[bb * 512 + d]);
                acc[bb] = fmaf(x.x, w0, acc[bb]);
                acc[bb] = fmaf(x.y, w1, acc[bb]);
                acc[bb] = fmaf(x.z, w2v, acc[bb]);
                acc[bb] = fmaf(x.w, w3v, acc[bb]);
            }
        }
        float bj = b1[j];
#pragma unroll
        for (int bb = 0; bb < 8; bb++) {
            float h = acc[bb] + bj;
            H1[bb * 256 + j] = (h > 0.f) ? h : expm1f(h);
        }
    }
    __syncthreads();
    {
        int j2 = tid & 127, g = tid >> 7;
        float acc[4] = {0.f, 0.f, 0.f, 0.f};
        for (int j = 0; j < 256; j++) {
            float w = W2[j * 128 + j2];
#pragma unroll
            for (int ii = 0; ii < 4; ii++) acc[ii] = fmaf(H1[(g * 4 + ii) * 256 + j], w, acc[ii]);
        }
        float bj = b2[j2];
#pragma unroll
        for (int ii = 0; ii < 4; ii++) {
            float h = acc[ii] + bj;
            H2[(g * 4 + ii) * 128 + j2] = (h > 0.f) ? h : expm1f(h);
        }
    }
    __syncthreads();
    {
        int wid = tid >> 5, lane = tid & 31;
        float s = 0.f;
        for (int j = lane; j < 128; j += 32) s = fmaf(H2[wid * 128 + j], W3[j], s);
        s = warp_sum(s);
        if (lane == 0) out[off + (size_t)(b0 + wid) * stride] = s + b3[0];
    }
}

// ---------------- orchestration ----------------
extern "C" void kernel_launch(void* const* d_in, const int* in_sizes, int n_in,
                              void* d_out, int out_size) {
    const float* emb     = (const float*)d_in[0];
    const float* keys    = (const float*)d_in[1];
    const float* memv    = (const float*)d_in[2];
    const float* W1      = (const float*)d_in[3];
    const float* b1      = (const float*)d_in[4];
    const float* W2      = (const float*)d_in[5];
    const float* b2      = (const float*)d_in[6];
    const float* W3      = (const float*)d_in[7];
    const float* b3      = (const float*)d_in[8];
    const int*   actions = (const int*)d_in[9];
    float* out = (float*)d_out;

    cudaFuncSetAttribute(sims_mma, cudaFuncAttributeMaxDynamicSharedMemorySize, SIMS_DYN_SMEM);

    row_denom_kernel<<<(Az * Nz + 255) / 256, 256>>>(keys, 0, Az * Nz);
    normalize_kernel<<<2048, 256>>>(keys, 0, (Az * Nz * Dz) / 4);
    row_denom_kernel<<<(Bsz + 255) / 256, 256>>>(emb, 1, Bsz);
    normalize_kernel<<<512, 256>>>(emb, 1, (Bsz * Dz) / 4);
    group_kernel<<<1, 256>>>(actions);

    mlp_kernel<<<Bsz / 8, 256>>>(emb, 1, W1, b1, W2, b2, W3, b3, out, 0, 1);

    for (int t = 0; t < NSTEP; t++) {
        sims_mma<<<dim3(Nz / 128, MT), 256, SIMS_DYN_SMEM>>>(t);
        topk_kernel<<<Bsz, 256>>>(memv, actions, t);
        mlp_kernel<<<Bsz / 8, 256>>>(emb, 0, W1, b1, W2, b2, W3, b3, out, Bsz + t, 5);
    }
}